// round 11
// baseline (speedup 1.0000x reference)
#include <cuda_runtime.h>
#include <cuda_bf16.h>

// Batched 1D linear interpolation with clamped extrapolation.
// t: [B, N] sorted per row, v: [B, N], r: [B, M]  ->  out: [B, M]
//
// One CTA per row, 72KB dynamic SMEM (3 CTAs/SM):
//   ts[i] = t[i], vs[i] = v[i], sa[i] = slope of segment [i,i+1]
//     -- all SPLIT packed f32 arrays: random SMEM gathers must be 4-byte
//        accesses spread over all 32 banks (paired/float2 layouts proved
//        2x conflict-heavy in R1/R6/R10).
//   P[k] = ushort bucket table, KB=12287 uniform buckets over [tmin,tmax]
//          (lambda ~= 0.33 knots/bucket), sentinel P[KB] = NN.
//
// FUSED PROLOGUE: tmin/tmax via uniform LDGs; staging, slopes, and the
// bucket-table scatter in ONE register-resident pass (neighbors via warp
// shuffle); scatter ranges provably tile [0, KB-1] -> no fill pass.
//
// Query: bucket -> [P[k], P[k+1]] -> 2 fixed branchless probe rounds
// (resolved lanes park on ts[0] broadcast; width <= 3 resolved, ~99.97%)
// + rarely-entered warp-voted fallback (correct for ANY sorted t)
// -> out = fmaf(r - t0, s, v0).

#define NN 4096
#define MM 4096
#define KB 12287
#define TABLE (KB + 1)               // 12288 u16 entries; P[KB] = NN sentinel
#define THREADS 512
#define QPT (MM / THREADS)           // 8 queries per thread

#define OFF_TS 0
#define OFF_VS (NN * 4)                    // 16384
#define OFF_SA (NN * 8)                    // 32768
#define OFF_P  (NN * 12)                   // 49152
#define SMEM_BYTES (OFF_P + TABLE * 2)     // 73728 = 72KB

__device__ __forceinline__ float seg_slope(float t0, float t1, float v0, float v1) {
    float d = t1 - t0;
    float denom = (d == 0.0f) ? 1.0f : d;
    return __fdividef(v1 - v0, denom);
}

__global__ __launch_bounds__(THREADS, 3)
void interp1d_kernel(const float* __restrict__ t,
                     const float* __restrict__ v,
                     const float* __restrict__ r,
                     float* __restrict__ out) {
    extern __shared__ char smem[];
    float*          ts = reinterpret_cast<float*>(smem + OFF_TS);
    float*          vs = reinterpret_cast<float*>(smem + OFF_VS);
    float*          sa = reinterpret_cast<float*>(smem + OFF_SA);
    unsigned short* P  = reinterpret_cast<unsigned short*>(smem + OFF_P);

    const int row = blockIdx.x;
    const float* trow = t + (size_t)row * NN;
    const float* vrow = v + (size_t)row * NN;
    const float* rrow = r + (size_t)row * MM;
    float*       orow = out + (size_t)row * MM;
    const int tid  = threadIdx.x;
    const int lane = tid & 31;

    // Uniform scalar loads (same address across warp -> broadcast)
    const float tmin   = trow[0];
    const float tmax   = trow[NN - 1];
    const float vfirst = vrow[0];
    const float vlast  = vrow[NN - 1];
    const float span   = tmax - tmin;
    const bool  ok     = (span > 0.0f);
    const float scale  = ok ? (float)KB / span : 0.0f;
    const float bias   = -tmin * scale;

    auto bucket_of = [&](float x) -> int {
        int k = (int)fmaf(x, scale, bias);   // monotone nondecreasing in x
        k = (k < 0) ? 0 : k;
        k = (k > KB - 1) ? KB - 1 : k;
        return k;
    };

    // ---- Fused staging + slopes + bucket-table scatter ----
    const float4* t4 = reinterpret_cast<const float4*>(trow);
    const float4* v4 = reinterpret_cast<const float4*>(vrow);
    float4* ts4 = reinterpret_cast<float4*>(ts);
    float4* vs4 = reinterpret_cast<float4*>(vs);
    float4* sa4 = reinterpret_cast<float4*>(sa);

    #pragma unroll
    for (int i = 0; i < NN / 4 / THREADS; i++) {       // 2 iterations
        int i4   = tid + i * THREADS;
        int base = i4 * 4;
        float4 a = t4[i4];
        float4 b = v4[i4];
        ts4[i4] = a;
        vs4[i4] = b;

        // next element (t[base+4], v[base+4]) from lane+1; lane 31 via LDG
        float tn = __shfl_down_sync(0xffffffffu, a.x, 1);
        float vn = __shfl_down_sync(0xffffffffu, b.x, 1);
        if (lane == 31) {
            if (base + 4 < NN) { tn = trow[base + 4]; vn = vrow[base + 4]; }
            else               { tn = a.w;            vn = b.w; }
        }

        float4 s;
        s.x = seg_slope(a.x, a.y, b.x, b.y);
        s.y = seg_slope(a.y, a.z, b.y, b.z);
        s.z = seg_slope(a.z, a.w, b.z, b.w);
        s.w = seg_slope(a.w, tn,  b.w, vn);
        sa4[i4] = s;

        // previous element t[base-1] from lane-1; lane 0 via LDG
        float tp = __shfl_up_sync(0xffffffffu, a.w, 1);
        if (lane == 0 && base > 0) tp = trow[base - 1];

        if (ok) {
            int bprev = (base == 0) ? -1 : bucket_of(tp);
            int b0 = bucket_of(a.x);
            int b1 = bucket_of(a.y);
            int b2 = bucket_of(a.z);
            int b3 = bucket_of(a.w);
            for (int k = bprev + 1; k <= b0; k++) P[k] = (unsigned short)(base);
            for (int k = b0 + 1;    k <= b1; k++) P[k] = (unsigned short)(base + 1);
            for (int k = b1 + 1;    k <= b2; k++) P[k] = (unsigned short)(base + 2);
            for (int k = b2 + 1;    k <= b3; k++) P[k] = (unsigned short)(base + 3);
        }
    }
    if (ok) {
        if (tid == 0) P[KB] = (unsigned short)NN;      // sentinel
    } else {
        // degenerate row (all knots equal): lo=hi=NN -> clamp to N-1 path,
        // matching reference's clip(searchsorted, 1, N-1) semantics.
        unsigned int* P32 = reinterpret_cast<unsigned int*>(P);
        const unsigned int fill = ((unsigned)NN << 16) | (unsigned)NN;
        for (int j = tid; j < TABLE / 2; j += THREADS) P32[j] = fill;
    }
    __syncthreads();

    // ---- Queries: 8 per thread, 4 register-interleaved at a time ----
    const float4* r4 = reinterpret_cast<const float4*>(rrow);
    float4*       o4 = reinterpret_cast<float4*>(orow);

    #pragma unroll
    for (int b = 0; b < QPT / 4; b++) {
        float4 rq = r4[tid + b * THREADS];             // 1 LDG.128, coalesced
        float rv[4] = {rq.x, rq.y, rq.z, rq.w};

        int lo[4], hi[4];
        #pragma unroll
        for (int q = 0; q < 4; q++) {
            int k = bucket_of(rv[q]);
            lo[q] = P[k];
            hi[q] = P[k + 1];                          // sentinel-safe
        }

        // 2 fixed branchless rounds; resolved lanes park on ts[0] (broadcast)
        #pragma unroll
        for (int rnd = 0; rnd < 2; rnd++) {
            #pragma unroll
            for (int q = 0; q < 4; q++) {
                bool go  = lo[q] < hi[q];
                int mid  = (lo[q] + hi[q]) >> 1;       // mid < hi <= NN: in range
                int addr = go ? mid : 0;
                float tm = ts[addr];
                bool le  = tm <= rv[q];
                lo[q] = (go &&  le) ? mid + 1 : lo[q];
                hi[q] = (go && !le) ? mid     : hi[q];
            }
        }

        // voted fallback, entered ~4% of batches (correct for any sorted t)
        int rem = (hi[0] - lo[0]) | (hi[1] - lo[1]) |
                  (hi[2] - lo[2]) | (hi[3] - lo[3]);
        while (__any_sync(0xffffffffu, rem != 0)) {
            #pragma unroll
            for (int q = 0; q < 4; q++) {
                bool go  = lo[q] < hi[q];
                int mid  = (lo[q] + hi[q]) >> 1;
                int addr = go ? mid : 0;
                float tm = ts[addr];
                bool le  = tm <= rv[q];
                lo[q] = (go &&  le) ? mid + 1 : lo[q];
                hi[q] = (go && !le) ? mid     : hi[q];
            }
            rem = (hi[0] - lo[0]) | (hi[1] - lo[1]) |
                  (hi[2] - lo[2]) | (hi[3] - lo[3]);
        }

        float res[4];
        #pragma unroll
        for (int q = 0; q < 4; q++) {
            int idx = lo[q];
            idx = (idx < 1) ? 1 : idx;
            idx = (idx > NN - 1) ? NN - 1 : idx;
            int i0 = idx - 1;
            float t0 = ts[i0];                         // 3 random LDS.32,
            float v0 = vs[i0];                         // all-bank spread
            float s  = sa[i0];
            float o  = fmaf(rv[q] - t0, s, v0);
            o = (rv[q] < tmin) ? vfirst : o;           // clamped extrapolation
            o = (rv[q] > tmax) ? vlast  : o;
            res[q] = o;
        }

        o4[tid + b * THREADS] = make_float4(res[0], res[1], res[2], res[3]);
    }
}

extern "C" void kernel_launch(void* const* d_in, const int* in_sizes, int n_in,
                              void* d_out, int out_size) {
    const float* t = (const float*)d_in[0];
    const float* v = (const float*)d_in[1];
    const float* r = (const float*)d_in[2];
    float* out = (float*)d_out;

    cudaFuncSetAttribute(interp1d_kernel,
                         cudaFuncAttributeMaxDynamicSharedMemorySize, SMEM_BYTES);

    int B = in_sizes[0] / NN;   // 2048 for the reference shape
    interp1d_kernel<<<B, THREADS, SMEM_BYTES>>>(t, v, r, out);
}

// round 12
// speedup vs baseline: 1.1543x; 1.1543x over previous
#include <cuda_runtime.h>
#include <cuda_bf16.h>

// Batched 1D linear interpolation with clamped extrapolation.
// t: [B, N] sorted per row, v: [B, N], r: [B, M]  ->  out: [B, M]
//
// One CTA per row, 64KB dynamic SMEM (3 CTAs/SM):
//   ts[i] = t[i] (+ sentinel ts[NN] = +inf), vs[i] = v[i],
//   sa[i] = slope of segment [i,i+1]  -- split packed f32 arrays (random
//   SMEM gathers must be 4-byte, all-bank-spread; proven in R1/R6/R10).
//   P[k]  = ushort bucket table, KB=8063 uniform buckets over [tmin,tmax].
//
// LINEAR-WALK SEARCH (no hi, no mid): pos starts at P[k]; every knot below
// P[k] provably has t <= r, so pos advances while ts[pos] <= r and stops at
// the exact searchsorted position. Only ONE table read per query. 3 fixed
// branchless rounds (E[steps]=0.25) + rarely-entered warp-voted fallback
// (correct for ANY sorted t; +inf sentinel bounds the walk).
//
// FUSED PROLOGUE: tmin/tmax via uniform LDGs; staging, slopes, and the
// bucket scatter in ONE register-resident pass (neighbors via shuffle);
// scatter ranges tile [0, KB-1] -> no fill pass.

#define NN 4096
#define MM 4096
#define KB 8063
#define TABLE (KB + 1)               // P[KB] written by the scatter tail
#define THREADS 512
#define QPT (MM / THREADS)           // 8 queries per thread

#define OFF_TS 0
#define OFF_VS 16400                       // (NN+4)*4, 16B aligned
#define OFF_SA (OFF_VS + NN * 4)           // 32784
#define OFF_P  (OFF_SA + NN * 4)           // 49168
#define SMEM_BYTES (OFF_P + TABLE * 2)     // 65296

__device__ __forceinline__ float seg_slope(float t0, float t1, float v0, float v1) {
    float d = t1 - t0;
    float denom = (d == 0.0f) ? 1.0f : d;
    return __fdividef(v1 - v0, denom);
}

__global__ __launch_bounds__(THREADS, 3)
void interp1d_kernel(const float* __restrict__ t,
                     const float* __restrict__ v,
                     const float* __restrict__ r,
                     float* __restrict__ out) {
    extern __shared__ char smem[];
    float*          ts = reinterpret_cast<float*>(smem + OFF_TS);
    float*          vs = reinterpret_cast<float*>(smem + OFF_VS);
    float*          sa = reinterpret_cast<float*>(smem + OFF_SA);
    unsigned short* P  = reinterpret_cast<unsigned short*>(smem + OFF_P);

    const int row = blockIdx.x;
    const float* trow = t + (size_t)row * NN;
    const float* vrow = v + (size_t)row * NN;
    const float* rrow = r + (size_t)row * MM;
    float*       orow = out + (size_t)row * MM;
    const int tid  = threadIdx.x;
    const int lane = tid & 31;

    // Uniform scalar loads (same address across warp -> broadcast)
    const float tmin   = trow[0];
    const float tmax   = trow[NN - 1];
    const float vfirst = vrow[0];
    const float vlast  = vrow[NN - 1];
    const float span   = tmax - tmin;
    const bool  ok     = (span > 0.0f);
    const float scale  = ok ? (float)KB / span : 0.0f;
    const float bias   = -tmin * scale;

    auto bucket_of = [&](float x) -> int {
        int k = (int)fmaf(x, scale, bias);   // monotone nondecreasing in x
        k = (k < 0) ? 0 : k;
        k = (k > KB - 1) ? KB - 1 : k;
        return k;
    };

    // ---- Fused staging + slopes + bucket-table scatter ----
    const float4* t4 = reinterpret_cast<const float4*>(trow);
    const float4* v4 = reinterpret_cast<const float4*>(vrow);
    float4* ts4 = reinterpret_cast<float4*>(ts);
    float4* vs4 = reinterpret_cast<float4*>(vs);
    float4* sa4 = reinterpret_cast<float4*>(sa);

    #pragma unroll
    for (int i = 0; i < NN / 4 / THREADS; i++) {       // 2 iterations
        int i4   = tid + i * THREADS;
        int base = i4 * 4;
        float4 a = t4[i4];
        float4 b = v4[i4];
        ts4[i4] = a;
        vs4[i4] = b;

        // next element (t[base+4], v[base+4]) from lane+1; lane 31 via LDG
        float tn = __shfl_down_sync(0xffffffffu, a.x, 1);
        float vn = __shfl_down_sync(0xffffffffu, b.x, 1);
        if (lane == 31) {
            if (base + 4 < NN) { tn = trow[base + 4]; vn = vrow[base + 4]; }
            else               { tn = a.w;            vn = b.w; }
        }

        float4 s;
        s.x = seg_slope(a.x, a.y, b.x, b.y);
        s.y = seg_slope(a.y, a.z, b.y, b.z);
        s.z = seg_slope(a.z, a.w, b.z, b.w);
        s.w = seg_slope(a.w, tn,  b.w, vn);
        sa4[i4] = s;

        // previous element t[base-1] from lane-1; lane 0 via LDG
        float tp = __shfl_up_sync(0xffffffffu, a.w, 1);
        if (lane == 0 && base > 0) tp = trow[base - 1];

        if (ok) {
            int bprev = (base == 0) ? -1 : bucket_of(tp);
            int b0 = bucket_of(a.x);
            int b1 = bucket_of(a.y);
            int b2 = bucket_of(a.z);
            int b3 = bucket_of(a.w);
            for (int k = bprev + 1; k <= b0; k++) P[k] = (unsigned short)(base);
            for (int k = b0 + 1;    k <= b1; k++) P[k] = (unsigned short)(base + 1);
            for (int k = b1 + 1;    k <= b2; k++) P[k] = (unsigned short)(base + 2);
            for (int k = b2 + 1;    k <= b3; k++) P[k] = (unsigned short)(base + 3);
        }
    }
    if (tid == 0) {
        ts[NN] = __int_as_float(0x7f800000);           // +inf walk sentinel
    }
    if (!ok) {
        // degenerate row (all knots equal): pos = NN -> sentinel stops walk,
        // idx clamps to N-1, matching reference semantics.
        unsigned int* P32 = reinterpret_cast<unsigned int*>(P);
        const unsigned int fill = ((unsigned)NN << 16) | (unsigned)NN;
        for (int j = tid; j < TABLE / 2; j += THREADS) P32[j] = fill;
    }
    __syncthreads();

    // ---- Queries: 8 per thread, 4 register-interleaved at a time ----
    const float4* r4 = reinterpret_cast<const float4*>(rrow);
    float4*       o4 = reinterpret_cast<float4*>(orow);

    #pragma unroll
    for (int b = 0; b < QPT / 4; b++) {
        float4 rq = r4[tid + b * THREADS];             // 1 LDG.128, coalesced
        float rv[4] = {rq.x, rq.y, rq.z, rq.w};

        int  pos[4];
        bool act[4] = {true, true, true, true};
        #pragma unroll
        for (int q = 0; q < 4; q++)
            pos[q] = P[bucket_of(rv[q])];              // ONE table read/query

        // 3 fixed branchless walk rounds; finished lanes park on ts[0]
        #pragma unroll
        for (int rnd = 0; rnd < 3; rnd++) {
            #pragma unroll
            for (int q = 0; q < 4; q++) {
                int addr = act[q] ? pos[q] : 0;        // pos <= NN (sentinel)
                float tm = ts[addr];
                bool adv = act[q] && (tm <= rv[q]);
                pos[q] += adv ? 1 : 0;
                act[q]  = adv;
            }
        }

        // voted fallback (correct for any sorted t; sentinel bounds walk)
        while (__any_sync(0xffffffffu, act[0] | act[1] | act[2] | act[3])) {
            #pragma unroll
            for (int q = 0; q < 4; q++) {
                int addr = act[q] ? pos[q] : 0;
                float tm = ts[addr];
                bool adv = act[q] && (tm <= rv[q]);
                pos[q] += adv ? 1 : 0;
                act[q]  = adv;
            }
        }

        float res[4];
        #pragma unroll
        for (int q = 0; q < 4; q++) {
            int idx = pos[q];
            idx = (idx < 1) ? 1 : idx;
            idx = (idx > NN - 1) ? NN - 1 : idx;
            int i0 = idx - 1;
            float t0 = ts[i0];                         // 3 random LDS.32,
            float v0 = vs[i0];                         // all-bank spread
            float s  = sa[i0];
            float o  = fmaf(rv[q] - t0, s, v0);
            o = (rv[q] < tmin) ? vfirst : o;           // clamped extrapolation
            o = (rv[q] > tmax) ? vlast  : o;
            res[q] = o;
        }

        o4[tid + b * THREADS] = make_float4(res[0], res[1], res[2], res[3]);
    }
}

extern "C" void kernel_launch(void* const* d_in, const int* in_sizes, int n_in,
                              void* d_out, int out_size) {
    const float* t = (const float*)d_in[0];
    const float* v = (const float*)d_in[1];
    const float* r = (const float*)d_in[2];
    float* out = (float*)d_out;

    cudaFuncSetAttribute(interp1d_kernel,
                         cudaFuncAttributeMaxDynamicSharedMemorySize, SMEM_BYTES);

    int B = in_sizes[0] / NN;   // 2048 for the reference shape
    interp1d_kernel<<<B, THREADS, SMEM_BYTES>>>(t, v, r, out);
}

// round 13
// speedup vs baseline: 1.1907x; 1.0316x over previous
#include <cuda_runtime.h>
#include <cuda_bf16.h>

// Batched 1D linear interpolation with clamped extrapolation.
// t: [B, N] sorted per row, v: [B, N], r: [B, M]  ->  out: [B, M]
//
// One CTA per row, 64KB dynamic SMEM (3 CTAs/SM):
//   ts[i] = t[i] (+ sentinel ts[NN] = +inf), vs[i] = v[i],
//   sa[i] = slope of segment [i,i+1]  -- split packed f32 arrays (random
//   SMEM gathers must be 4-byte, all-bank-spread; proven in R1/R6/R10).
//   P[k]  = u16 bucket table, KB=8063 uniform buckets over [tmin,tmax].
//           bits[0:13] = searchsorted position of the bucket's left edge;
//           bit 15 = PURE flag: bucket contains NO knot, so pos is exact
//           and the walk is skipped entirely (~60% of queries at lambda=0.5).
//
// LINEAR-WALK SEARCH: pos starts at P[k]&0x7FFF; advances while
// ts[pos] <= r (3 fixed branchless rounds, parked lanes broadcast ts[0])
// + rarely-entered warp-voted fallback (correct for ANY sorted t; +inf
// sentinel bounds the walk).
//
// FUSED PROLOGUE: tmin/tmax via uniform LDGs; staging, slopes, and the
// flagged bucket scatter in ONE register-resident pass (neighbors via
// shuffle); scatter ranges tile [0, KB-1] -> no fill pass.

#define NN 4096
#define MM 4096
#define KB 8063
#define TABLE (KB + 1)
#define THREADS 512
#define QPT (MM / THREADS)           // 8 queries per thread
#define PURE 0x8000u

#define OFF_TS 0
#define OFF_VS 16400                       // (NN+4)*4, 16B aligned
#define OFF_SA (OFF_VS + NN * 4)           // 32784
#define OFF_P  (OFF_SA + NN * 4)           // 49168
#define SMEM_BYTES (OFF_P + TABLE * 2)     // 65296

__device__ __forceinline__ float seg_slope(float t0, float t1, float v0, float v1) {
    float d = t1 - t0;
    float denom = (d == 0.0f) ? 1.0f : d;
    return __fdividef(v1 - v0, denom);
}

__global__ __launch_bounds__(THREADS, 3)
void interp1d_kernel(const float* __restrict__ t,
                     const float* __restrict__ v,
                     const float* __restrict__ r,
                     float* __restrict__ out) {
    extern __shared__ char smem[];
    float*          ts = reinterpret_cast<float*>(smem + OFF_TS);
    float*          vs = reinterpret_cast<float*>(smem + OFF_VS);
    float*          sa = reinterpret_cast<float*>(smem + OFF_SA);
    unsigned short* P  = reinterpret_cast<unsigned short*>(smem + OFF_P);

    const int row = blockIdx.x;
    const float* trow = t + (size_t)row * NN;
    const float* vrow = v + (size_t)row * NN;
    const float* rrow = r + (size_t)row * MM;
    float*       orow = out + (size_t)row * MM;
    const int tid  = threadIdx.x;
    const int lane = tid & 31;

    // Uniform scalar loads (same address across warp -> broadcast)
    const float tmin   = trow[0];
    const float tmax   = trow[NN - 1];
    const float vfirst = vrow[0];
    const float vlast  = vrow[NN - 1];
    const float span   = tmax - tmin;
    const bool  ok     = (span > 0.0f);
    const float scale  = ok ? (float)KB / span : 0.0f;
    const float bias   = -tmin * scale;

    auto bucket_of = [&](float x) -> int {
        int k = (int)fmaf(x, scale, bias);   // monotone nondecreasing in x
        k = (k < 0) ? 0 : k;
        k = (k > KB - 1) ? KB - 1 : k;
        return k;
    };

    // scatter for knot e owning table range (p, c]:
    //   entries (p, c) are knot-free buckets -> PURE flag; entry c holds
    //   knot e itself -> no flag (walk required).
    auto scat = [&](int e, int p, int c) {
        unsigned short pe = (unsigned short)(e | PURE);
        for (int k = p + 1; k < c; k++) P[k] = pe;
        if (c > p) P[c] = (unsigned short)e;
    };

    // ---- Fused staging + slopes + flagged bucket scatter ----
    const float4* t4 = reinterpret_cast<const float4*>(trow);
    const float4* v4 = reinterpret_cast<const float4*>(vrow);
    float4* ts4 = reinterpret_cast<float4*>(ts);
    float4* vs4 = reinterpret_cast<float4*>(vs);
    float4* sa4 = reinterpret_cast<float4*>(sa);

    #pragma unroll
    for (int i = 0; i < NN / 4 / THREADS; i++) {       // 2 iterations
        int i4   = tid + i * THREADS;
        int base = i4 * 4;
        float4 a = t4[i4];
        float4 b = v4[i4];
        ts4[i4] = a;
        vs4[i4] = b;

        // next element (t[base+4], v[base+4]) from lane+1; lane 31 via LDG
        float tn = __shfl_down_sync(0xffffffffu, a.x, 1);
        float vn = __shfl_down_sync(0xffffffffu, b.x, 1);
        if (lane == 31) {
            if (base + 4 < NN) { tn = trow[base + 4]; vn = vrow[base + 4]; }
            else               { tn = a.w;            vn = b.w; }
        }

        float4 s;
        s.x = seg_slope(a.x, a.y, b.x, b.y);
        s.y = seg_slope(a.y, a.z, b.y, b.z);
        s.z = seg_slope(a.z, a.w, b.z, b.w);
        s.w = seg_slope(a.w, tn,  b.w, vn);
        sa4[i4] = s;

        // previous element t[base-1] from lane-1; lane 0 via LDG
        float tp = __shfl_up_sync(0xffffffffu, a.w, 1);
        if (lane == 0 && base > 0) tp = trow[base - 1];

        if (ok) {
            int bprev = (base == 0) ? -1 : bucket_of(tp);
            int b0 = bucket_of(a.x);
            int b1 = bucket_of(a.y);
            int b2 = bucket_of(a.z);
            int b3 = bucket_of(a.w);
            scat(base + 0, bprev, b0);
            scat(base + 1, b0,    b1);
            scat(base + 2, b1,    b2);
            scat(base + 3, b2,    b3);
        }
    }
    if (tid == 0) {
        ts[NN] = __int_as_float(0x7f800000);           // +inf walk sentinel
    }
    if (!ok) {
        // degenerate row (all knots equal): pos = NN, PURE -> no walk,
        // idx clamps to N-1, matching reference semantics.
        unsigned int* P32 = reinterpret_cast<unsigned int*>(P);
        const unsigned int e = (unsigned)NN | PURE;
        const unsigned int fill = (e << 16) | e;
        for (int j = tid; j < TABLE / 2; j += THREADS) P32[j] = fill;
    }
    __syncthreads();

    // ---- Queries: 8 per thread, 4 register-interleaved at a time ----
    const float4* r4 = reinterpret_cast<const float4*>(rrow);
    float4*       o4 = reinterpret_cast<float4*>(orow);

    #pragma unroll
    for (int b = 0; b < QPT / 4; b++) {
        float4 rq = r4[tid + b * THREADS];             // 1 LDG.128, coalesced
        float rv[4] = {rq.x, rq.y, rq.z, rq.w};

        int  pos[4];
        bool act[4];
        #pragma unroll
        for (int q = 0; q < 4; q++) {
            unsigned int lh = P[bucket_of(rv[q])];     // ONE table read/query
            pos[q] = (int)(lh & 0x7FFFu);
            act[q] = (lh & PURE) == 0u;                // pure -> walk skipped
        }

        // 3 fixed branchless walk rounds; inactive lanes park on ts[0]
        #pragma unroll
        for (int rnd = 0; rnd < 3; rnd++) {
            #pragma unroll
            for (int q = 0; q < 4; q++) {
                int addr = act[q] ? pos[q] : 0;        // pos <= NN (sentinel)
                float tm = ts[addr];
                bool adv = act[q] && (tm <= rv[q]);
                pos[q] += adv ? 1 : 0;
                act[q]  = adv;
            }
        }

        // voted fallback (correct for any sorted t; sentinel bounds walk)
        while (__any_sync(0xffffffffu, act[0] | act[1] | act[2] | act[3])) {
            #pragma unroll
            for (int q = 0; q < 4; q++) {
                int addr = act[q] ? pos[q] : 0;
                float tm = ts[addr];
                bool adv = act[q] && (tm <= rv[q]);
                pos[q] += adv ? 1 : 0;
                act[q]  = adv;
            }
        }

        float res[4];
        #pragma unroll
        for (int q = 0; q < 4; q++) {
            int idx = pos[q];
            idx = (idx < 1) ? 1 : idx;
            idx = (idx > NN - 1) ? NN - 1 : idx;
            int i0 = idx - 1;
            float t0 = ts[i0];                         // 3 random LDS.32,
            float v0 = vs[i0];                         // all-bank spread
            float s  = sa[i0];
            float o  = fmaf(rv[q] - t0, s, v0);
            o = (rv[q] < tmin) ? vfirst : o;           // clamped extrapolation
            o = (rv[q] > tmax) ? vlast  : o;
            res[q] = o;
        }

        o4[tid + b * THREADS] = make_float4(res[0], res[1], res[2], res[3]);
    }
}

extern "C" void kernel_launch(void* const* d_in, const int* in_sizes, int n_in,
                              void* d_out, int out_size) {
    const float* t = (const float*)d_in[0];
    const float* v = (const float*)d_in[1];
    const float* r = (const float*)d_in[2];
    float* out = (float*)d_out;

    cudaFuncSetAttribute(interp1d_kernel,
                         cudaFuncAttributeMaxDynamicSharedMemorySize, SMEM_BYTES);

    int B = in_sizes[0] / NN;   // 2048 for the reference shape
    interp1d_kernel<<<B, THREADS, SMEM_BYTES>>>(t, v, r, out);
}